// round 13
// baseline (speedup 1.0000x reference)
#include <cuda_runtime.h>
#include <cstdint>

#define B_   128
#define C_   512
#define PIX  238            // 7*34
#define NCH  529
#define KTOT (NCH*PIX)      // 125902
#define KSPLIT 37
#define KSP  3424           // fp32 k per split (37*3424 = 126688 >= KTOT)
#define KSP2 1712           // pair-words per split
#define KPAD2 63344         // pair-words per dense row
#define NCHUNK 107          // KSP/32
#define NPLANE 324          // padded 9*36 plane positions
#define NCHK 34             // global 16-channel chunks covering 529 (+15 zero)
#define XP2_CH (NPLANE * 8) // 2592 words per (b,chunk) plane
#define WCT 2304            // 9 taps * 32 oc * 8 kpair words per tile

#define XS_W   (NPLANE * 12)   // 3888 words
#define WS64_W (2 * 3456)      // 6912 words (2 oc-halves)
#define STG_W  (XS_W + WS64_W) // 10800 words / 43200 B per stage

// fc1 stage: Xs bf16 [128][20] = 2560 w, Ws bf16 [64][20] = 1280 w
#define F1_XSW 2560
#define F1_STW 3840            // words per stage; 4 stages = 61440 B
#define F1_NSTG 4

// ---------------- scratch (device globals; no allocations allowed) ----------
__device__ uint32_t g_Xdb[B_ * KPAD2];           // dense activations, bf16 pairs (fc1)
__device__ uint32_t g_Xp2[B_ * NCHK * XP2_CH];   // padded bf16 pair-interleaved (convs)
__device__ uint32_t g_Wc2[234 * WCT];            // prepped conv weights, bf16 pairs
__device__ uint32_t g_Wfb[KSPLIT * 8 * NCHUNK * 1024]; // fc1 W, bf16 tiled (130MB)
__device__ float g_part[KSPLIT * B_ * 512];
__device__ float g_fc1[B_ * 512];
__device__ float g_h[2 * B_ * 256];
__device__ float g_ang[2 * B_];

typedef unsigned long long ull;

__device__ __forceinline__ float leaky(float x) { return x >= 0.f ? x : 0.1f * x; }

__device__ __forceinline__ ull fpack(float lo, float hi) {
    ull r; asm("mov.b64 %0, {%1, %2};" : "=l"(r) : "f"(lo), "f"(hi)); return r;
}
__device__ __forceinline__ void funpack(ull p, float& lo, float& hi) {
    asm("mov.b64 {%0, %1}, %2;" : "=f"(lo), "=f"(hi) : "l"(p));
}
__device__ __forceinline__ void fma2(ull& d, ull a, ull b) {
    asm("fma.rn.f32x2 %0, %1, %2, %3;" : "=l"(d) : "l"(a), "l"(b), "l"(d));
}
__device__ __forceinline__ uint16_t f2bf(float f) {
    uint32_t u = __float_as_uint(f);
    return (uint16_t)((u + 0x7fffu + ((u >> 16) & 1u)) >> 16);
}
__device__ __forceinline__ uint32_t f2bf2(float lo, float hi) {
    return (uint32_t)f2bf(lo) | ((uint32_t)f2bf(hi) << 16);
}
__device__ __forceinline__ uint32_t cvt_bf2(float lo, float hi) {  // {hi,lo} packed
    uint32_t r;
    asm("cvt.rn.bf16x2.f32 %0, %1, %2;" : "=r"(r) : "f"(hi), "f"(lo));
    return r;
}
__device__ __forceinline__ void mma_bf16(float* c,
                                         uint32_t a0, uint32_t a1, uint32_t a2, uint32_t a3,
                                         uint32_t b0, uint32_t b1) {
    asm volatile("mma.sync.aligned.m16n8k16.row.col.f32.bf16.bf16.f32 "
                 "{%0,%1,%2,%3}, {%4,%5,%6,%7}, {%8,%9}, {%0,%1,%2,%3};"
                 : "+f"(c[0]), "+f"(c[1]), "+f"(c[2]), "+f"(c[3])
                 : "r"(a0), "r"(a1), "r"(a2), "r"(a3), "r"(b0), "r"(b1));
}
__device__ __forceinline__ uint32_t sptr(const void* p) {
    return (uint32_t)__cvta_generic_to_shared(p);
}
#define CPA16(dst, src)  asm volatile("cp.async.ca.shared.global [%0], [%1], 16;"    :: "r"(dst), "l"(src))
#define CPCOMMIT()       asm volatile("cp.async.commit_group;")
#define CPWAIT1()        asm volatile("cp.async.wait_group 1;" ::: "memory")
#define CPWAIT3()        asm volatile("cp.async.wait_group 3;" ::: "memory")

// ============================================================================
// fc1 weight prep (forked stream): fp32 W -> bf16 pairs, per-block tiled
// layout: [ks][ntile][chunk][row64][16 words]; runs under corr+convs.
// ============================================================================
__global__ __launch_bounds__(256) void fc1wprep_k(const float* __restrict__ Wf) {
    int ntile = blockIdx.x, ks = blockIdx.y;
    int nb = ntile * 64, k0 = ks * KSP;
    uint32_t* out = g_Wfb + (size_t)(ks * 8 + ntile) * (NCHUNK * 1024);
    int t = threadIdx.x, row = t >> 2, q = t & 3;
    const float* src = Wf + (size_t)(nb + row) * KTOT;
    for (int ch = 0; ch < NCHUNK; ch++) {
        int col = k0 + ch * 32 + q * 8;
        float v[8];
        if (col + 8 <= KTOT) {
            float2 p0 = *(const float2*)(src + col);
            float2 p1 = *(const float2*)(src + col + 2);
            float2 p2 = *(const float2*)(src + col + 4);
            float2 p3 = *(const float2*)(src + col + 6);
            v[0] = p0.x; v[1] = p0.y; v[2] = p1.x; v[3] = p1.y;
            v[4] = p2.x; v[5] = p2.y; v[6] = p3.x; v[7] = p3.y;
        } else {
#pragma unroll
            for (int i = 0; i < 8; i++) v[i] = (col + i < KTOT) ? src[col + i] : 0.f;
        }
        uint4 w;
        w.x = cvt_bf2(v[0], v[1]); w.y = cvt_bf2(v[2], v[3]);
        w.z = cvt_bf2(v[4], v[5]); w.w = cvt_bf2(v[6], v[7]);
        *(uint4*)(out + ch * 1024 + row * 16 + q * 4) = w;
    }
}

// ============================================================================
// conv weight prep: all 5 layers -> pair-packed bf16 tiles [tap][oc32][kpair]
// ============================================================================
__global__ void wprep_all(const float* __restrict__ w0, const float* __restrict__ w1,
                          const float* __restrict__ w2, const float* __restrict__ w3,
                          const float* __restrict__ w4) {
    int tile = blockIdx.x;
    const float* W; int IC, chunks, tbase;
    if      (tile <  24) { W = w0; IC =  81; chunks =  6; tbase =   0; }
    else if (tile <  80) { W = w1; IC = 209; chunks = 14; tbase =  24; }
    else if (tile < 146) { W = w2; IC = 337; chunks = 22; tbase =  80; }
    else if (tile < 202) { W = w3; IC = 433; chunks = 28; tbase = 146; }
    else                 { W = w4; IC = 497; chunks = 32; tbase = 202; }
    int rel = tile - tbase, ocb = rel / chunks, ch = rel % chunks;
    uint32_t* out = g_Wc2 + (size_t)tile * WCT;
    for (int i = threadIdx.x; i < WCT; i += 256) {
        int tap = i >> 8, rem = i & 255, oc = rem >> 3, kp = rem & 7;
        int ic0 = ch * 16 + kp * 2;
        float v0 = 0.f, v1 = 0.f;
        const float* wrow = W + ((size_t)(ocb * 32 + oc) * IC) * 9;
        if (ic0     < IC) v0 = wrow[(ic0    ) * 9 + tap];
        if (ic0 + 1 < IC) v1 = wrow[(ic0 + 1) * 9 + tap];
        out[i] = f2bf2(v0, v1);
    }
}

// ============================================================================
// corr81 + leaky -> channels [448,529): bf16 dense pairs + bf16 padded
// ============================================================================
__global__ __launch_bounds__(576) void corr_k(const float* __restrict__ L,
                                              const float* __restrict__ R) {
    int b = blockIdx.x;
    __shared__ __align__(16) float Ls[16][7][36];
    __shared__ __align__(16) float Rs[16][7][44];
    int t = threadIdx.x;
    int g  = t % 9;
    int dy = (t / 9) % 9;
    int y  = t / 81;
    int x0 = g * 4;

    for (int i = t; i < 16 * 7 * 44; i += 576) ((float*)Rs)[i] = 0.f;
    for (int i = t; i < 16 * 7 * 36; i += 576) ((float*)Ls)[i] = 0.f;
    __syncthreads();

    ull acc2[9][2] = {};

    int ry = y + dy - 4;
    bool valid = (y < 7) && (ry >= 0) && (ry < 7);
    const float* Lb = L + (size_t)b * C_ * PIX;
    const float* Rb = R + (size_t)b * C_ * PIX;

    for (int c0 = 0; c0 < C_; c0 += 16) {
        for (int i = t; i < 16 * PIX; i += 576) {
            int c = i / PIX, p = i % PIX;
            Ls[c][p / 34][p % 34]       = Lb[(size_t)(c0 + c) * PIX + p];
            Rs[c][p / 34][(p % 34) + 4] = Rb[(size_t)(c0 + c) * PIX + p];
        }
        __syncthreads();
        if (valid) {
#pragma unroll
            for (int c = 0; c < 16; c++) {
                float4 l4 = *(const float4*)&Ls[c][y][x0];
                float4 r0 = *(const float4*)&Rs[c][ry][x0];
                float4 r1 = *(const float4*)&Rs[c][ry][x0 + 4];
                float4 r2 = *(const float4*)&Rs[c][ry][x0 + 8];
                ull lp0 = fpack(l4.x, l4.y), lp1 = fpack(l4.z, l4.w);
                float rv[12] = {r0.x, r0.y, r0.z, r0.w,
                                r1.x, r1.y, r1.z, r1.w,
                                r2.x, r2.y, r2.z, r2.w};
#pragma unroll
                for (int dx = 0; dx < 9; dx++) {
                    fma2(acc2[dx][0], lp0, fpack(rv[dx],     rv[dx + 1]));
                    fma2(acc2[dx][1], lp1, fpack(rv[dx + 2], rv[dx + 3]));
                }
            }
        }
        __syncthreads();
    }

    if (y < 7) {
        uint16_t* Xp16 = (uint16_t*)g_Xp2;
#pragma unroll
        for (int dx = 0; dx < 9; dx++) {
            int ch = 448 + dy * 9 + dx;
            float av[4];
            funpack(acc2[dx][0], av[0], av[1]);
            funpack(acc2[dx][1], av[2], av[3]);
            float v[4];
#pragma unroll
            for (int i = 0; i < 4; i++) v[i] = leaky(av[i] * (1.f / 512.f));

            size_t pbase = ((size_t)(b * NCHK + (ch >> 4)) * NPLANE) * 8 + ((ch & 15) >> 1);
            int half = ch & 1;
#pragma unroll
            for (int i = 0; i < 4; i++) {
                int x = x0 + i;
                if (x < 34) {
                    int pos = (y + 1) * 36 + (x + 1);
                    Xp16[(pbase + (size_t)pos * 8) * 2 + half] = f2bf(v[i]);
                }
            }
            uint32_t* odb = g_Xdb + (size_t)b * KPAD2 + ch * 119 + y * 17;
            odb[x0 >> 1] = f2bf2(v[0], v[1]);
            if (x0 < 32) odb[(x0 >> 1) + 1] = f2bf2(v[2], v[3]);
        }
    }
}

// ============================================================================
// 3x3 conv, bf16 mma.m16n8k16, 64-oc block tile; cp.async 2-stage; 2 blk/SM
// ============================================================================
__device__ __forceinline__ void conv64_fill(const uint32_t* Xsrc,
                                            const uint32_t* W0, const uint32_t* W1,
                                            int nhalf, uint32_t* stage, int ch, int t) {
    const uint32_t* xs = Xsrc + (size_t)ch * XP2_CH;
    for (int i = t; i < 648; i += 256) {
        int pos = i >> 1, h = i & 1;
        CPA16(sptr(stage + pos * 12 + h * 4), xs + pos * 8 + h * 4);
    }
    uint32_t* Ws = stage + XS_W;
    for (int i = t; i < nhalf * 576; i += 256) {
        int h = (i >= 576), ii = i - h * 576;
        int to = ii >> 1, hw = ii & 1;
        const uint32_t* ws = (h ? W1 : W0) + (size_t)ch * WCT;
        CPA16(sptr(Ws + h * 3456 + to * 12 + hw * 4), ws + to * 8 + hw * 4);
    }
}

__global__ __launch_bounds__(256, 2) void convB64_k(const float* __restrict__ Bi,
                                                    int chunks, int wtile0,
                                                    int chunk0in, int OUT_OFF, int OC) {
    int b    = blockIdx.x;
    int ocb2 = blockIdx.y;
    bool partial = (ocb2 * 64 + 64 > OC);
    int nhalf = partial ? 1 : 2;
    extern __shared__ uint32_t dyn[];

    int t = threadIdx.x;
    int wid = t >> 5, lane = t & 31;
    int mw = wid & 1, nw = wid >> 1;
    int gid = lane >> 2, tig = lane & 3;

    float acc[2][8][4] = {};

    int offp[8];
#pragma unroll
    for (int j = 0; j < 8; j++) {
        int p = nw * 64 + j * 8 + gid;
        if (p > 237) p = 237;
        offp[j] = (p / 34) * 36 + (p % 34);
    }

    const uint32_t* Xsrc = g_Xp2 + (size_t)(b * NCHK + chunk0in) * XP2_CH;
    const uint32_t* W0 = g_Wc2 + (size_t)(wtile0 + (ocb2 * 2    ) * chunks) * WCT;
    const uint32_t* W1 = g_Wc2 + (size_t)(wtile0 + (ocb2 * 2 + nhalf - 1) * chunks) * WCT;

    int aBase0, aBase1;
    if (partial) {
        aBase0 = (mw * 16 + gid) * 12 + tig;
        aBase1 = aBase0;
    } else {
        aBase0 = mw * 3456 + (gid     ) * 12 + tig;
        aBase1 = mw * 3456 + (16 + gid) * 12 + tig;
    }

    conv64_fill(Xsrc, W0, W1, nhalf, dyn, 0, t);
    CPCOMMIT();

    int buf = 0;
    for (int ch = 0; ch < chunks; ch++) {
        if (ch + 1 < chunks)
            conv64_fill(Xsrc, W0, W1, nhalf, dyn + (buf ^ 1) * STG_W, ch + 1, t);
        CPCOMMIT();
        CPWAIT1();
        __syncthreads();

        const uint32_t* Xs = dyn + buf * STG_W;
        const uint32_t* Ws = Xs + XS_W;
        if (!partial) {
#pragma unroll
            for (int ky = 0; ky < 3; ky++)
#pragma unroll
                for (int kx = 0; kx < 3; kx++) {
                    int kk  = ky * 3 + kx;
                    int kof = ky * 36 + kx;
                    int a0b = aBase0 + kk * 384;
                    int a1b = aBase1 + kk * 384;
                    uint32_t p0 = Ws[a0b], p1 = Ws[a0b + 96];
                    uint32_t p2 = Ws[a0b + 4], p3 = Ws[a0b + 100];
                    uint32_t q0 = Ws[a1b], q1 = Ws[a1b + 96];
                    uint32_t q2 = Ws[a1b + 4], q3 = Ws[a1b + 100];
#pragma unroll
                    for (int j = 0; j < 8; j++) {
                        int xb = (offp[j] + kof) * 12 + tig;
                        uint32_t b0 = Xs[xb];
                        uint32_t b1 = Xs[xb + 4];
                        mma_bf16(acc[0][j], p0, p1, p2, p3, b0, b1);
                        mma_bf16(acc[1][j], q0, q1, q2, q3, b0, b1);
                    }
                }
        } else {
#pragma unroll
            for (int ky = 0; ky < 3; ky++)
#pragma unroll
                for (int kx = 0; kx < 3; kx++) {
                    int kk  = ky * 3 + kx;
                    int kof = ky * 36 + kx;
                    int a0b = aBase0 + kk * 384;
                    uint32_t p0 = Ws[a0b], p1 = Ws[a0b + 96];
                    uint32_t p2 = Ws[a0b + 4], p3 = Ws[a0b + 100];
#pragma unroll
                    for (int j = 0; j < 8; j++) {
                        int xb = (offp[j] + kof) * 12 + tig;
                        uint32_t b0 = Xs[xb];
                        uint32_t b1 = Xs[xb + 4];
                        mma_bf16(acc[0][j], p0, p1, p2, p3, b0, b1);
                    }
                }
        }
        __syncthreads();
        buf ^= 1;
    }

    // epilogue: bias + leaky; bf16 dense pairs + bf16 padded stores
    uint16_t* Xp16 = (uint16_t*)g_Xp2;
    uint32_t* odb = g_Xdb + (size_t)b * KPAD2;
    int fmax = partial ? 1 : 2;
    int kp0 = gid >> 1, kp1 = kp0 + 4, half = gid & 1;
    for (int f = 0; f < fmax; f++) {
        int ocf = ocb2 * 64 + (partial ? mw * 16 : mw * 32 + f * 16);
        int oc0 = ocf + gid;
        int oc1 = oc0 + 8;
        float bi0 = Bi[oc0], bi1 = Bi[oc1];
        int cw0 = (OUT_OFF + oc0) * 119;
        int cw1 = (OUT_OFF + oc1) * 119;
        size_t pb = ((size_t)(b * NCHK + (OUT_OFF >> 4) + (ocf >> 4)) * NPLANE) * 8;
#pragma unroll
        for (int j = 0; j < 8; j++) {
            int p = nw * 64 + j * 8 + tig * 2;
            if (p < 238) {
                int p1 = p + 1;
                int pos0 = (p / 34 + 1) * 36 + (p % 34 + 1);
                int pos1 = (p1 / 34 + 1) * 36 + (p1 % 34 + 1);
                float v00 = leaky(acc[f][j][0] + bi0);
                float v01 = leaky(acc[f][j][1] + bi0);
                float v10 = leaky(acc[f][j][2] + bi1);
                float v11 = leaky(acc[f][j][3] + bi1);
                odb[cw0 + (p >> 1)] = f2bf2(v00, v01);
                odb[cw1 + (p >> 1)] = f2bf2(v10, v11);
                Xp16[(pb + (size_t)pos0 * 8 + kp0) * 2 + half] = f2bf(v00);
                Xp16[(pb + (size_t)pos1 * 8 + kp0) * 2 + half] = f2bf(v01);
                Xp16[(pb + (size_t)pos0 * 8 + kp1) * 2 + half] = f2bf(v10);
                Xp16[(pb + (size_t)pos1 * 8 + kp1) * 2 + half] = f2bf(v11);
            }
        }
    }
}

// ============================================================================
// fc1 via bf16 mma: X bf16 pairs + pre-tiled bf16 W (contiguous 4KB fills),
// 4-stage cp.async pipeline, grid (8, 37) = 296 = one full wave.
// ============================================================================
__device__ __forceinline__ void fc1_fill(const uint32_t* Wsrc, uint32_t* stage,
                                         int kk2, int ch, int t) {
    for (int i = t; i < 512; i += 256) {
        int row = i >> 2, w4 = (i & 3) * 4;
        CPA16(sptr(stage + row * 20 + w4),
              g_Xdb + (size_t)row * KPAD2 + kk2 + ch * 16 + w4);
    }
    int row = t >> 2, q = t & 3;
    CPA16(sptr(stage + F1_XSW + row * 20 + q * 4), Wsrc + (size_t)ch * 1024 + t * 4);
}

__global__ __launch_bounds__(256, 2) void fc1B_k() {
    int ntile = blockIdx.x, ks = blockIdx.y;
    int k20 = ks * KSP2;
    extern __shared__ uint32_t dyn[];

    int t = threadIdx.x;
    int wid = t >> 5, lane = t & 31;
    int gid = lane >> 2, tig = lane & 3;
    int mwarp = wid & 3, nwarp = wid >> 2;
    int m0 = mwarp * 32, n0 = nwarp * 32;

    const uint32_t* Wsrc = g_Wfb + (size_t)(ks * 8 + ntile) * (NCHUNK * 1024);

    float acc[2][4][4] = {};

#pragma unroll
    for (int s = 0; s < 3; s++) {
        fc1_fill(Wsrc, dyn + s * F1_STW, k20, s, t);
        CPCOMMIT();
    }

    for (int ch = 0; ch < NCHUNK; ch++) {
        if (ch + 3 < NCHUNK)
            fc1_fill(Wsrc, dyn + ((ch + 3) & 3) * F1_STW, k20, ch + 3, t);
        CPCOMMIT();
        CPWAIT3();
        __syncthreads();

        const uint32_t* Xs = dyn + (ch & 3) * F1_STW;
        const uint32_t* Ws = Xs + F1_XSW;
#pragma unroll
        for (int g16 = 0; g16 < 2; g16++) {
            int wb = g16 * 8;
            uint32_t a[2][4];
#pragma unroll
            for (int mi = 0; mi < 2; mi++) {
                int rb = (m0 + mi * 16 + gid) * 20 + wb;
                a[mi][0] = Xs[rb + tig];
                a[mi][1] = Xs[rb + 160 + tig];        // row gid+8 (8 rows * stride 20)
                a[mi][2] = Xs[rb + tig + 4];
                a[mi][3] = Xs[rb + 160 + tig + 4];
            }
#pragma unroll
            for (int nj = 0; nj < 4; nj++) {
                int wbb = (n0 + nj * 8 + gid) * 20 + wb;
                uint32_t b0 = Ws[wbb + tig];
                uint32_t b1 = Ws[wbb + tig + 4];
#pragma unroll
                for (int mi = 0; mi < 2; mi++)
                    mma_bf16(acc[mi][nj], a[mi][0], a[mi][1], a[mi][2], a[mi][3], b0, b1);
            }
        }
        __syncthreads();
    }

    float* pp = g_part + (size_t)ks * 65536;
    int nb = ntile * 64;
#pragma unroll
    for (int mi = 0; mi < 2; mi++) {
        int m = m0 + mi * 16;
#pragma unroll
        for (int nj = 0; nj < 4; nj++) {
            int col = nb + n0 + nj * 8 + 2 * tig;
            *(float2*)&pp[(size_t)(m + gid    ) * 512 + col] =
                make_float2(acc[mi][nj][0], acc[mi][nj][1]);
            *(float2*)&pp[(size_t)(m + gid + 8) * 512 + col] =
                make_float2(acc[mi][nj][2], acc[mi][nj][3]);
        }
    }
}

__global__ void fc1red_k(const float* __restrict__ bias) {
    int i = blockIdx.x * 256 + threadIdx.x;
    float a = 0.f;
#pragma unroll
    for (int ks = 0; ks < KSPLIT; ks++) a += g_part[(size_t)ks * 65536 + i];
    g_fc1[i] = leaky(a + bias[i & 511]);
}

// ============================================================================
// l1 / r1 (FFMA2, small)
// ============================================================================
__global__ __launch_bounds__(256, 2) void l1r1_k(const float* __restrict__ wl1,
                                                 const float* __restrict__ bl1,
                                                 const float* __restrict__ wr1,
                                                 const float* __restrict__ br1) {
    int side = blockIdx.x, ntile = blockIdx.y;
    int nb = ntile * 128;
    const float* Wp = side ? wr1 : wl1;
    const float* Bp = side ? br1 : bl1;
    __shared__ __align__(16) float Xs[16][132];
    __shared__ __align__(16) float Ws[16][132];
    int t = threadIdx.x, tn = t & 15, tb = t >> 4, b0 = tb * 8, n0 = tn * 8;
    ull acc[8][4] = {};

    for (int kk0 = 0; kk0 < 512; kk0 += 16) {
        for (int i = t; i < 2048; i += 256) {
            int k = i & 15, row = i >> 4;
            Xs[k][row] = g_fc1[(size_t)row * 512 + kk0 + k];
            Ws[k][row] = Wp[(size_t)(nb + row) * 512 + kk0 + k];
        }
        __syncthreads();
#pragma unroll 4
        for (int kk = 0; kk < 16; kk++) {
            float4 xa = *(const float4*)&Xs[kk][b0];
            float4 xb = *(const float4*)&Xs[kk][b0 + 4];
            float4 wa = *(const float4*)&Ws[kk][n0];
            float4 wb = *(const float4*)&Ws[kk][n0 + 4];
            ull xd[8] = {fpack(xa.x, xa.x), fpack(xa.y, xa.y),
                         fpack(xa.z, xa.z), fpack(xa.w, xa.w),
                         fpack(xb.x, xb.x), fpack(xb.y, xb.y),
                         fpack(xb.z, xb.z), fpack(xb.w, xb.w)};
            ull w2[4] = {fpack(wa.x, wa.y), fpack(wa.z, wa.w),
                         fpack(wb.x, wb.y), fpack(wb.z, wb.w)};
#pragma unroll
            for (int i = 0; i < 8; i++)
#pragma unroll
                for (int j = 0; j < 4; j++)
                    fma2(acc[i][j], w2[j], xd[i]);
        }
        __syncthreads();
    }

#pragma unroll
    for (int i = 0; i < 8; i++)
#pragma unroll
        for (int j = 0; j < 4; j++) {
            float lo, hi; funpack(acc[i][j], lo, hi);
            int n = nb + n0 + 2 * j;
            float* p = &g_h[(size_t)side * (B_ * 256) + (size_t)(b0 + i) * 256 + n];
            p[0] = leaky(lo + Bp[n]);
            p[1] = leaky(hi + Bp[n + 1]);
        }
}

// ============================================================================
// heads + quat distance + mean
// ============================================================================
__global__ void heads2_k(const float* __restrict__ wl2, const float* __restrict__ bl2,
                         const float* __restrict__ wr2, const float* __restrict__ br2,
                         const float* __restrict__ lt,  const float* __restrict__ rt) {
    int b = blockIdx.x, t = threadIdx.x;
    __shared__ float hl[256], hr[256], q[8];
    hl[t] = g_h[(size_t)b * 256 + t];
    hr[t] = g_h[(size_t)(B_ * 256) + (size_t)b * 256 + t];
    __syncthreads();

    int wrp = t >> 5, lane = t & 31;
    const float* w   = (wrp < 4) ? wl2 : wr2;
    const float* src = (wrp < 4) ? hl : hr;
    int i = wrp & 3;
    float s = 0.f;
    for (int j = lane; j < 256; j += 32) s += w[i * 256 + j] * src[j];
#pragma unroll
    for (int off = 16; off > 0; off >>= 1) s += __shfl_down_sync(0xffffffffu, s, off);
    if (lane == 0) q[wrp] = s + ((wrp < 4) ? bl2[i] : br2[i]);
    __syncthreads();

    if (t == 0) {
#pragma unroll
        for (int side = 0; side < 2; side++) {
            float qw = q[side * 4 + 0], qx = q[side * 4 + 1];
            float qy = q[side * 4 + 2], qz = q[side * 4 + 3];
            float nn = sqrtf(qw * qw + qx * qx + qy * qy + qz * qz);
            nn = fmaxf(nn, 1e-12f);
            qw /= nn; qx /= nn; qy /= nn; qz /= nn;
            const float* tgt = (side == 0 ? lt : rt) + (size_t)b * 4;
            float rw = tgt[0], rx = -tgt[1], ry = -tgt[2], rz = -tgt[3];
            float tw = qw * rw - qx * rx - qy * ry - qz * rz;
            float tx = qw * rx + qx * rw + qy * rz - qz * ry;
            float ty = qw * ry - qx * rz + qy * rw + qz * rx;
            float tz = qw * rz + qx * ry - qy * rx + qz * rw;
            float ang = 2.f * atan2f(sqrtf(tx * tx + ty * ty + tz * tz + 1e-12f), fabsf(tw));
            g_ang[side * B_ + b] = ang;
        }
    }
}

__global__ void mean_k(float* __restrict__ out) {
    __shared__ float sl[128], sr[128];
    int t = threadIdx.x;
    sl[t] = g_ang[t];
    sr[t] = g_ang[128 + t];
    __syncthreads();
    for (int s = 64; s > 0; s >>= 1) {
        if (t < s) { sl[t] += sl[t + s]; sr[t] += sr[t + s]; }
        __syncthreads();
    }
    if (t == 0) { out[0] = sl[0] * (1.f / 128.f); out[1] = sr[0] * (1.f / 128.f); }
}

// ============================================================================
extern "C" void kernel_launch(void* const* d_in, const int* in_sizes, int n_in,
                              void* d_out, int out_size) {
    (void)in_sizes; (void)n_in; (void)out_size;
    const float* left  = (const float*)d_in[0];
    const float* right = (const float*)d_in[1];
    const float* lt    = (const float*)d_in[2];
    const float* rt    = (const float*)d_in[3];
    const float* w6[5] = {(const float*)d_in[4],  (const float*)d_in[6],
                          (const float*)d_in[8],  (const float*)d_in[10],
                          (const float*)d_in[12]};
    const float* b6[5] = {(const float*)d_in[5],  (const float*)d_in[7],
                          (const float*)d_in[9],  (const float*)d_in[11],
                          (const float*)d_in[13]};
    const float* wfc1 = (const float*)d_in[14];
    const float* bfc1 = (const float*)d_in[15];
    const float* wl1  = (const float*)d_in[16];
    const float* bl1  = (const float*)d_in[17];
    const float* wr1  = (const float*)d_in[18];
    const float* br1  = (const float*)d_in[19];
    const float* wl2  = (const float*)d_in[20];
    const float* bl2  = (const float*)d_in[21];
    const float* wr2  = (const float*)d_in[22];
    const float* br2  = (const float*)d_in[23];
    float* out = (float*)d_out;

    static cudaStream_t s2 = nullptr;
    static cudaEvent_t evFork = nullptr, evJoin = nullptr;
    if (s2 == nullptr) {
        cudaStreamCreateWithFlags(&s2, cudaStreamNonBlocking);
        cudaEventCreateWithFlags(&evFork, cudaEventDisableTiming);
        cudaEventCreateWithFlags(&evJoin, cudaEventDisableTiming);
        cudaFuncSetAttribute(convB64_k, cudaFuncAttributeMaxDynamicSharedMemorySize,
                             2 * STG_W * 4);
        cudaFuncSetAttribute(fc1B_k, cudaFuncAttributeMaxDynamicSharedMemorySize,
                             F1_NSTG * F1_STW * 4);
    }

    const int INO[5]   = {448, 320, 192, 96, 32};
    const int OUTO[5]  = {320, 192, 96, 32, 0};
    const int OCL[5]   = {128, 128, 96, 64, 32};
    const int OCT64[5] = {2, 2, 2, 1, 1};
    const int CHK[5]   = {6, 14, 22, 28, 32};
    const int WBASE[5] = {0, 24, 80, 146, 202};

    // fork: fc1 weight conversion overlaps corr + convs on stream s2
    cudaEventRecord(evFork, 0);
    cudaStreamWaitEvent(s2, evFork, 0);
    fc1wprep_k<<<dim3(8, KSPLIT), 256, 0, s2>>>(wfc1);
    cudaEventRecord(evJoin, s2);

    wprep_all<<<234, 256>>>(w6[0], w6[1], w6[2], w6[3], w6[4]);
    corr_k<<<B_, 576>>>(left, right);

    for (int l = 0; l < 5; l++)
        convB64_k<<<dim3(B_, OCT64[l]), 256, 2 * STG_W * 4>>>(
            b6[l], CHK[l], WBASE[l], INO[l] >> 4, OUTO[l], OCL[l]);

    // join before fc1 consumes g_Wfb
    cudaStreamWaitEvent(0, evJoin, 0);
    fc1B_k<<<dim3(8, KSPLIT), 256, F1_NSTG * F1_STW * 4>>>();
    fc1red_k<<<256, 256>>>(bfc1);
    l1r1_k<<<dim3(2, 2), 256>>>(wl1, bl1, wr1, br1);
    heads2_k<<<B_, 256>>>(wl2, bl2, wr2, br2, lt, rt);
    mean_k<<<1, 128>>>(out);
}

// round 14
// speedup vs baseline: 1.2395x; 1.2395x over previous
#include <cuda_runtime.h>
#include <cstdint>

#define B_   128
#define C_   512
#define PIX  238            // 7*34
#define NCH  529
#define KTOT (NCH*PIX)      // 125902
#define KSPLIT 37
#define KSP  3424           // fp32 k per split (37*3424 = 126688 >= KTOT)
#define KSP2 1712           // pair-words per split
#define KPAD2 63344         // pair-words per dense row
#define NCHUNK 107          // KSP/32
#define NPLANE 324          // padded 9*36 plane positions
#define NCHK 34             // global 16-channel chunks covering 529 (+15 zero)
#define XP2_CH (NPLANE * 8) // 2592 words per (b,chunk) plane
#define WCT 2304            // 9 taps * 32 oc * 8 kpair words per tile

#define XS_W   (NPLANE * 12)   // 3888 words
#define WS64_W (2 * 3456)      // 6912 words (2 oc-halves)
#define STG_W  (XS_W + WS64_W) // 10800 words / 43200 B per stage

// fc1 stage: Xs bf16 [128][20] = 2560 w, Ws bf16 [64][20] = 1280 w
#define F1_XSW 2560
#define F1_STW 3840            // words per stage; 4 stages = 61440 B
#define F1_NSTG 4

// corr stages: Ls[16][7][36] + Rs[16][7][44] floats
#define CORR_LS 4032
#define CORR_RS 4928
#define CORR_STG (CORR_LS + CORR_RS)   // 8960 words; 2 stages = 71680 B

// ---------------- scratch (device globals; no allocations allowed) ----------
__device__ uint32_t g_Xdb[B_ * KPAD2];           // dense activations, bf16 pairs (fc1)
__device__ uint32_t g_Xp2[B_ * NCHK * XP2_CH];   // padded bf16 pair-interleaved (convs)
__device__ uint32_t g_Wc2[234 * WCT];            // prepped conv weights, bf16 pairs
__device__ uint32_t g_Wfb[KSPLIT * 8 * NCHUNK * 1024]; // fc1 W, bf16 tiled (130MB)
__device__ float g_part[KSPLIT * B_ * 512];
__device__ float g_fc1[B_ * 512];
__device__ float g_h[2 * B_ * 256];
__device__ float g_ang[2 * B_];

typedef unsigned long long ull;

__device__ __forceinline__ float leaky(float x) { return x >= 0.f ? x : 0.1f * x; }

__device__ __forceinline__ ull fpack(float lo, float hi) {
    ull r; asm("mov.b64 %0, {%1, %2};" : "=l"(r) : "f"(lo), "f"(hi)); return r;
}
__device__ __forceinline__ void funpack(ull p, float& lo, float& hi) {
    asm("mov.b64 {%0, %1}, %2;" : "=f"(lo), "=f"(hi) : "l"(p));
}
__device__ __forceinline__ void fma2(ull& d, ull a, ull b) {
    asm("fma.rn.f32x2 %0, %1, %2, %3;" : "=l"(d) : "l"(a), "l"(b), "l"(d));
}
__device__ __forceinline__ uint16_t f2bf(float f) {
    uint32_t u = __float_as_uint(f);
    return (uint16_t)((u + 0x7fffu + ((u >> 16) & 1u)) >> 16);
}
__device__ __forceinline__ uint32_t f2bf2(float lo, float hi) {
    return (uint32_t)f2bf(lo) | ((uint32_t)f2bf(hi) << 16);
}
__device__ __forceinline__ uint32_t cvt_bf2(float lo, float hi) {  // {hi,lo} packed
    uint32_t r;
    asm("cvt.rn.bf16x2.f32 %0, %1, %2;" : "=r"(r) : "f"(hi), "f"(lo));
    return r;
}
__device__ __forceinline__ void mma_bf16(float* c,
                                         uint32_t a0, uint32_t a1, uint32_t a2, uint32_t a3,
                                         uint32_t b0, uint32_t b1) {
    asm volatile("mma.sync.aligned.m16n8k16.row.col.f32.bf16.bf16.f32 "
                 "{%0,%1,%2,%3}, {%4,%5,%6,%7}, {%8,%9}, {%0,%1,%2,%3};"
                 : "+f"(c[0]), "+f"(c[1]), "+f"(c[2]), "+f"(c[3])
                 : "r"(a0), "r"(a1), "r"(a2), "r"(a3), "r"(b0), "r"(b1));
}
__device__ __forceinline__ uint32_t sptr(const void* p) {
    return (uint32_t)__cvta_generic_to_shared(p);
}
#define CPA16(dst, src)  asm volatile("cp.async.ca.shared.global [%0], [%1], 16;"    :: "r"(dst), "l"(src))
#define CPA8(dst, src)   asm volatile("cp.async.ca.shared.global [%0], [%1], 8;"     :: "r"(dst), "l"(src))
#define CPCOMMIT()       asm volatile("cp.async.commit_group;")
#define CPWAIT1()        asm volatile("cp.async.wait_group 1;" ::: "memory")
#define CPWAIT3()        asm volatile("cp.async.wait_group 3;" ::: "memory")

// ============================================================================
// fc1 weight prep (forked stream): fp32 W -> bf16 pairs, per-block tiled
// layout: [ks][ntile][chunk][row64][16 words]; fills SM gaps under corr+convs.
// ============================================================================
__global__ __launch_bounds__(256) void fc1wprep_k(const float* __restrict__ Wf) {
    int ntile = blockIdx.x, ks = blockIdx.y;
    int nb = ntile * 64, k0 = ks * KSP;
    uint32_t* out = g_Wfb + (size_t)(ks * 8 + ntile) * (NCHUNK * 1024);
    int t = threadIdx.x, row = t >> 2, q = t & 3;
    const float* src = Wf + (size_t)(nb + row) * KTOT;
    for (int ch = 0; ch < NCHUNK; ch++) {
        int col = k0 + ch * 32 + q * 8;
        float v[8];
        if (col + 8 <= KTOT) {
            float2 p0 = *(const float2*)(src + col);
            float2 p1 = *(const float2*)(src + col + 2);
            float2 p2 = *(const float2*)(src + col + 4);
            float2 p3 = *(const float2*)(src + col + 6);
            v[0] = p0.x; v[1] = p0.y; v[2] = p1.x; v[3] = p1.y;
            v[4] = p2.x; v[5] = p2.y; v[6] = p3.x; v[7] = p3.y;
        } else {
#pragma unroll
            for (int i = 0; i < 8; i++) v[i] = (col + i < KTOT) ? src[col + i] : 0.f;
        }
        uint4 w;
        w.x = cvt_bf2(v[0], v[1]); w.y = cvt_bf2(v[2], v[3]);
        w.z = cvt_bf2(v[4], v[5]); w.w = cvt_bf2(v[6], v[7]);
        *(uint4*)(out + ch * 1024 + row * 16 + q * 4) = w;
    }
}

// ============================================================================
// conv weight prep: all 5 layers -> pair-packed bf16 tiles [tap][oc32][kpair]
// ============================================================================
__global__ void wprep_all(const float* __restrict__ w0, const float* __restrict__ w1,
                          const float* __restrict__ w2, const float* __restrict__ w3,
                          const float* __restrict__ w4) {
    int tile = blockIdx.x;
    const float* W; int IC, chunks, tbase;
    if      (tile <  24) { W = w0; IC =  81; chunks =  6; tbase =   0; }
    else if (tile <  80) { W = w1; IC = 209; chunks = 14; tbase =  24; }
    else if (tile < 146) { W = w2; IC = 337; chunks = 22; tbase =  80; }
    else if (tile < 202) { W = w3; IC = 433; chunks = 28; tbase = 146; }
    else                 { W = w4; IC = 497; chunks = 32; tbase = 202; }
    int rel = tile - tbase, ocb = rel / chunks, ch = rel % chunks;
    uint32_t* out = g_Wc2 + (size_t)tile * WCT;
    for (int i = threadIdx.x; i < WCT; i += 256) {
        int tap = i >> 8, rem = i & 255, oc = rem >> 3, kp = rem & 7;
        int ic0 = ch * 16 + kp * 2;
        float v0 = 0.f, v1 = 0.f;
        const float* wrow = W + ((size_t)(ocb * 32 + oc) * IC) * 9;
        if (ic0     < IC) v0 = wrow[(ic0    ) * 9 + tap];
        if (ic0 + 1 < IC) v1 = wrow[(ic0 + 1) * 9 + tap];
        out[i] = f2bf2(v0, v1);
    }
}

// ============================================================================
// corr81 + leaky: cp.async double-buffered 16-channel chunks
// ============================================================================
__device__ __forceinline__ void corr_fill(const float* __restrict__ Lb,
                                          const float* __restrict__ Rb,
                                          float* Ls, float* Rs, int c0, int t) {
    for (int j = t; j < 16 * 119; j += 576) {
        int c = j / 119, pp = (j % 119) * 2;
        int y = pp / 34, x = pp % 34;
        const float* ls = Lb + (size_t)(c0 + c) * PIX + pp;
        const float* rs = Rb + (size_t)(c0 + c) * PIX + pp;
        CPA8(sptr(Ls + c * 252 + y * 36 + x), ls);
        CPA8(sptr(Rs + c * 308 + y * 44 + x + 4), rs);
    }
}

__global__ __launch_bounds__(576) void corr_k(const float* __restrict__ L,
                                              const float* __restrict__ R) {
    int b = blockIdx.x;
    extern __shared__ float csm[];
    int t = threadIdx.x;
    int g  = t % 9;
    int dy = (t / 9) % 9;
    int y  = t / 81;
    int x0 = g * 4;

    for (int i = t; i < 2 * CORR_STG; i += 576) csm[i] = 0.f;
    __syncthreads();

    ull acc2[9][2] = {};
    int ry = y + dy - 4;
    bool valid = (y < 7) && (ry >= 0) && (ry < 7);
    const float* Lb = L + (size_t)b * C_ * PIX;
    const float* Rb = R + (size_t)b * C_ * PIX;

    corr_fill(Lb, Rb, csm, csm + CORR_LS, 0, t);
    CPCOMMIT();

    int st = 0;
    for (int c0 = 0; c0 < C_; c0 += 16) {
        if (c0 + 16 < C_)
            corr_fill(Lb, Rb, csm + (st ^ 1) * CORR_STG,
                      csm + (st ^ 1) * CORR_STG + CORR_LS, c0 + 16, t);
        CPCOMMIT();
        CPWAIT1();
        __syncthreads();

        const float* Ls = csm + st * CORR_STG;
        const float* Rs = Ls + CORR_LS;
        if (valid) {
#pragma unroll
            for (int c = 0; c < 16; c++) {
                const float* lrow = Ls + c * 252 + y * 36;
                const float* rrow = Rs + c * 308 + ry * 44;
                float4 l4 = *(const float4*)(lrow + x0);
                float4 r0 = *(const float4*)(rrow + x0);
                float4 r1 = *(const float4*)(rrow + x0 + 4);
                float4 r2 = *(const float4*)(rrow + x0 + 8);
                ull lp0 = fpack(l4.x, l4.y), lp1 = fpack(l4.z, l4.w);
                float rv[12] = {r0.x, r0.y, r0.z, r0.w,
                                r1.x, r1.y, r1.z, r1.w,
                                r2.x, r2.y, r2.z, r2.w};
#pragma unroll
                for (int dx = 0; dx < 9; dx++) {
                    fma2(acc2[dx][0], lp0, fpack(rv[dx],     rv[dx + 1]));
                    fma2(acc2[dx][1], lp1, fpack(rv[dx + 2], rv[dx + 3]));
                }
            }
        }
        __syncthreads();
        st ^= 1;
    }

    if (y < 7) {
        uint16_t* Xp16 = (uint16_t*)g_Xp2;
#pragma unroll
        for (int dx = 0; dx < 9; dx++) {
            int ch = 448 + dy * 9 + dx;
            float av[4];
            funpack(acc2[dx][0], av[0], av[1]);
            funpack(acc2[dx][1], av[2], av[3]);
            float v[4];
#pragma unroll
            for (int i = 0; i < 4; i++) v[i] = leaky(av[i] * (1.f / 512.f));

            size_t pbase = ((size_t)(b * NCHK + (ch >> 4)) * NPLANE) * 8 + ((ch & 15) >> 1);
            int half = ch & 1;
#pragma unroll
            for (int i = 0; i < 4; i++) {
                int x = x0 + i;
                if (x < 34) {
                    int pos = (y + 1) * 36 + (x + 1);
                    Xp16[(pbase + (size_t)pos * 8) * 2 + half] = f2bf(v[i]);
                }
            }
            uint32_t* odb = g_Xdb + (size_t)b * KPAD2 + ch * 119 + y * 17;
            odb[x0 >> 1] = f2bf2(v[0], v[1]);
            if (x0 < 32) odb[(x0 >> 1) + 1] = f2bf2(v[2], v[3]);
        }
    }
}

// ============================================================================
// 3x3 conv, bf16 mma.m16n8k16, 64-oc block tile; cp.async 2-stage; 2 blk/SM
// ============================================================================
__device__ __forceinline__ void conv64_fill(const uint32_t* Xsrc,
                                            const uint32_t* W0, const uint32_t* W1,
                                            int nhalf, uint32_t* stage, int ch, int t) {
    const uint32_t* xs = Xsrc + (size_t)ch * XP2_CH;
    for (int i = t; i < 648; i += 256) {
        int pos = i >> 1, h = i & 1;
        CPA16(sptr(stage + pos * 12 + h * 4), xs + pos * 8 + h * 4);
    }
    uint32_t* Ws = stage + XS_W;
    for (int i = t; i < nhalf * 576; i += 256) {
        int h = (i >= 576), ii = i - h * 576;
        int to = ii >> 1, hw = ii & 1;
        const uint32_t* ws = (h ? W1 : W0) + (size_t)ch * WCT;
        CPA16(sptr(Ws + h * 3456 + to * 12 + hw * 4), ws + to * 8 + hw * 4);
    }
}

__global__ __launch_bounds__(256, 2) void convB64_k(const float* __restrict__ Bi,
                                                    int chunks, int wtile0,
                                                    int chunk0in, int OUT_OFF, int OC) {
    int b    = blockIdx.x;
    int ocb2 = blockIdx.y;
    bool partial = (ocb2 * 64 + 64 > OC);
    int nhalf = partial ? 1 : 2;
    extern __shared__ uint32_t dyn[];

    int t = threadIdx.x;
    int wid = t >> 5, lane = t & 31;
    int mw = wid & 1, nw = wid >> 1;
    int gid = lane >> 2, tig = lane & 3;

    float acc[2][8][4] = {};

    int offp[8];
#pragma unroll
    for (int j = 0; j < 8; j++) {
        int p = nw * 64 + j * 8 + gid;
        if (p > 237) p = 237;
        offp[j] = (p / 34) * 36 + (p % 34);
    }

    const uint32_t* Xsrc = g_Xp2 + (size_t)(b * NCHK + chunk0in) * XP2_CH;
    const uint32_t* W0 = g_Wc2 + (size_t)(wtile0 + (ocb2 * 2    ) * chunks) * WCT;
    const uint32_t* W1 = g_Wc2 + (size_t)(wtile0 + (ocb2 * 2 + nhalf - 1) * chunks) * WCT;

    int aBase0, aBase1;
    if (partial) {
        aBase0 = (mw * 16 + gid) * 12 + tig;
        aBase1 = aBase0;
    } else {
        aBase0 = mw * 3456 + (gid     ) * 12 + tig;
        aBase1 = mw * 3456 + (16 + gid) * 12 + tig;
    }

    conv64_fill(Xsrc, W0, W1, nhalf, dyn, 0, t);
    CPCOMMIT();

    int buf = 0;
    for (int ch = 0; ch < chunks; ch++) {
        if (ch + 1 < chunks)
            conv64_fill(Xsrc, W0, W1, nhalf, dyn + (buf ^ 1) * STG_W, ch + 1, t);
        CPCOMMIT();
        CPWAIT1();
        __syncthreads();

        const uint32_t* Xs = dyn + buf * STG_W;
        const uint32_t* Ws = Xs + XS_W;
        if (!partial) {
#pragma unroll
            for (int ky = 0; ky < 3; ky++)
#pragma unroll
                for (int kx = 0; kx < 3; kx++) {
                    int kk  = ky * 3 + kx;
                    int kof = ky * 36 + kx;
                    int a0b = aBase0 + kk * 384;
                    int a1b = aBase1 + kk * 384;
                    uint32_t p0 = Ws[a0b], p1 = Ws[a0b + 96];
                    uint32_t p2 = Ws[a0b + 4], p3 = Ws[a0b + 100];
                    uint32_t q0 = Ws[a1b], q1 = Ws[a1b + 96];
                    uint32_t q2 = Ws[a1b + 4], q3 = Ws[a1b + 100];
#pragma unroll
                    for (int j = 0; j < 8; j++) {
                        int xb = (offp[j] + kof) * 12 + tig;
                        uint32_t b0 = Xs[xb];
                        uint32_t b1 = Xs[xb + 4];
                        mma_bf16(acc[0][j], p0, p1, p2, p3, b0, b1);
                        mma_bf16(acc[1][j], q0, q1, q2, q3, b0, b1);
                    }
                }
        } else {
#pragma unroll
            for (int ky = 0; ky < 3; ky++)
#pragma unroll
                for (int kx = 0; kx < 3; kx++) {
                    int kk  = ky * 3 + kx;
                    int kof = ky * 36 + kx;
                    int a0b = aBase0 + kk * 384;
                    uint32_t p0 = Ws[a0b], p1 = Ws[a0b + 96];
                    uint32_t p2 = Ws[a0b + 4], p3 = Ws[a0b + 100];
#pragma unroll
                    for (int j = 0; j < 8; j++) {
                        int xb = (offp[j] + kof) * 12 + tig;
                        uint32_t b0 = Xs[xb];
                        uint32_t b1 = Xs[xb + 4];
                        mma_bf16(acc[0][j], p0, p1, p2, p3, b0, b1);
                    }
                }
        }
        __syncthreads();
        buf ^= 1;
    }

    // epilogue: bias + leaky; bf16 dense pairs + bf16 padded stores
    uint16_t* Xp16 = (uint16_t*)g_Xp2;
    uint32_t* odb = g_Xdb + (size_t)b * KPAD2;
    int fmax = partial ? 1 : 2;
    int kp0 = gid >> 1, kp1 = kp0 + 4, half = gid & 1;
    for (int f = 0; f < fmax; f++) {
        int ocf = ocb2 * 64 + (partial ? mw * 16 : mw * 32 + f * 16);
        int oc0 = ocf + gid;
        int oc1 = oc0 + 8;
        float bi0 = Bi[oc0], bi1 = Bi[oc1];
        int cw0 = (OUT_OFF + oc0) * 119;
        int cw1 = (OUT_OFF + oc1) * 119;
        size_t pb = ((size_t)(b * NCHK + (OUT_OFF >> 4) + (ocf >> 4)) * NPLANE) * 8;
#pragma unroll
        for (int j = 0; j < 8; j++) {
            int p = nw * 64 + j * 8 + tig * 2;
            if (p < 238) {
                int p1 = p + 1;
                int pos0 = (p / 34 + 1) * 36 + (p % 34 + 1);
                int pos1 = (p1 / 34 + 1) * 36 + (p1 % 34 + 1);
                float v00 = leaky(acc[f][j][0] + bi0);
                float v01 = leaky(acc[f][j][1] + bi0);
                float v10 = leaky(acc[f][j][2] + bi1);
                float v11 = leaky(acc[f][j][3] + bi1);
                odb[cw0 + (p >> 1)] = f2bf2(v00, v01);
                odb[cw1 + (p >> 1)] = f2bf2(v10, v11);
                Xp16[(pb + (size_t)pos0 * 8 + kp0) * 2 + half] = f2bf(v00);
                Xp16[(pb + (size_t)pos1 * 8 + kp0) * 2 + half] = f2bf(v01);
                Xp16[(pb + (size_t)pos0 * 8 + kp1) * 2 + half] = f2bf(v10);
                Xp16[(pb + (size_t)pos1 * 8 + kp1) * 2 + half] = f2bf(v11);
            }
        }
    }
}

// ============================================================================
// fc1 via bf16 mma: X bf16 pairs + pre-tiled bf16 W (contiguous 4KB fills),
// 4-stage cp.async pipeline, grid (8, 37) = 296 = one full wave.
// ============================================================================
__device__ __forceinline__ void fc1_fill(const uint32_t* Wsrc, uint32_t* stage,
                                         int kk2, int ch, int t) {
    for (int i = t; i < 512; i += 256) {
        int row = i >> 2, w4 = (i & 3) * 4;
        CPA16(sptr(stage + row * 20 + w4),
              g_Xdb + (size_t)row * KPAD2 + kk2 + ch * 16 + w4);
    }
    int row = t >> 2, q = t & 3;
    CPA16(sptr(stage + F1_XSW + row * 20 + q * 4), Wsrc + (size_t)ch * 1024 + t * 4);
}

__global__ __launch_bounds__(256, 2) void fc1B_k() {
    int ntile = blockIdx.x, ks = blockIdx.y;
    int k20 = ks * KSP2;
    extern __shared__ uint32_t dyn[];

    int t = threadIdx.x;
    int wid = t >> 5, lane = t & 31;
    int gid = lane >> 2, tig = lane & 3;
    int mwarp = wid & 3, nwarp = wid >> 2;
    int m0 = mwarp * 32, n0 = nwarp * 32;

    const uint32_t* Wsrc = g_Wfb + (size_t)(ks * 8 + ntile) * (NCHUNK * 1024);

    float acc[2][4][4] = {};

#pragma unroll
    for (int s = 0; s < 3; s++) {
        fc1_fill(Wsrc, dyn + s * F1_STW, k20, s, t);
        CPCOMMIT();
    }

    for (int ch = 0; ch < NCHUNK; ch++) {
        if (ch + 3 < NCHUNK)
            fc1_fill(Wsrc, dyn + ((ch + 3) & 3) * F1_STW, k20, ch + 3, t);
        CPCOMMIT();
        CPWAIT3();
        __syncthreads();

        const uint32_t* Xs = dyn + (ch & 3) * F1_STW;
        const uint32_t* Ws = Xs + F1_XSW;
#pragma unroll
        for (int g16 = 0; g16 < 2; g16++) {
            int wb = g16 * 8;
            uint32_t a[2][4];
#pragma unroll
            for (int mi = 0; mi < 2; mi++) {
                int rb = (m0 + mi * 16 + gid) * 20 + wb;
                a[mi][0] = Xs[rb + tig];
                a[mi][1] = Xs[rb + 160 + tig];        // row gid+8 (8 rows * stride 20)
                a[mi][2] = Xs[rb + tig + 4];
                a[mi][3] = Xs[rb + 160 + tig + 4];
            }
#pragma unroll
            for (int nj = 0; nj < 4; nj++) {
                int wbb = (n0 + nj * 8 + gid) * 20 + wb;
                uint32_t b0 = Ws[wbb + tig];
                uint32_t b1 = Ws[wbb + tig + 4];
#pragma unroll
                for (int mi = 0; mi < 2; mi++)
                    mma_bf16(acc[mi][nj], a[mi][0], a[mi][1], a[mi][2], a[mi][3], b0, b1);
            }
        }
        __syncthreads();
    }

    float* pp = g_part + (size_t)ks * 65536;
    int nb = ntile * 64;
#pragma unroll
    for (int mi = 0; mi < 2; mi++) {
        int m = m0 + mi * 16;
#pragma unroll
        for (int nj = 0; nj < 4; nj++) {
            int col = nb + n0 + nj * 8 + 2 * tig;
            *(float2*)&pp[(size_t)(m + gid    ) * 512 + col] =
                make_float2(acc[mi][nj][0], acc[mi][nj][1]);
            *(float2*)&pp[(size_t)(m + gid + 8) * 512 + col] =
                make_float2(acc[mi][nj][2], acc[mi][nj][3]);
        }
    }
}

__global__ void fc1red_k(const float* __restrict__ bias) {
    int i = blockIdx.x * 256 + threadIdx.x;
    float a = 0.f;
#pragma unroll
    for (int ks = 0; ks < KSPLIT; ks++) a += g_part[(size_t)ks * 65536 + i];
    g_fc1[i] = leaky(a + bias[i & 511]);
}

// ============================================================================
// l1 / r1 (FFMA2, small)
// ============================================================================
__global__ __launch_bounds__(256, 2) void l1r1_k(const float* __restrict__ wl1,
                                                 const float* __restrict__ bl1,
                                                 const float* __restrict__ wr1,
                                                 const float* __restrict__ br1) {
    int side = blockIdx.x, ntile = blockIdx.y;
    int nb = ntile * 128;
    const float* Wp = side ? wr1 : wl1;
    const float* Bp = side ? br1 : bl1;
    __shared__ __align__(16) float Xs[16][132];
    __shared__ __align__(16) float Ws[16][132];
    int t = threadIdx.x, tn = t & 15, tb = t >> 4, b0 = tb * 8, n0 = tn * 8;
    ull acc[8][4] = {};

    for (int kk0 = 0; kk0 < 512; kk0 += 16) {
        for (int i = t; i < 2048; i += 256) {
            int k = i & 15, row = i >> 4;
            Xs[k][row] = g_fc1[(size_t)row * 512 + kk0 + k];
            Ws[k][row] = Wp[(size_t)(nb + row) * 512 + kk0 + k];
        }
        __syncthreads();
#pragma unroll 4
        for (int kk = 0; kk < 16; kk++) {
            float4 xa = *(const float4*)&Xs[kk][b0];
            float4 xb = *(const float4*)&Xs[kk][b0 + 4];
            float4 wa = *(const float4*)&Ws[kk][n0];
            float4 wb = *(const float4*)&Ws[kk][n0 + 4];
            ull xd[8] = {fpack(xa.x, xa.x), fpack(xa.y, xa.y),
                         fpack(xa.z, xa.z), fpack(xa.w, xa.w),
                         fpack(xb.x, xb.x), fpack(xb.y, xb.y),
                         fpack(xb.z, xb.z), fpack(xb.w, xb.w)};
            ull w2[4] = {fpack(wa.x, wa.y), fpack(wa.z, wa.w),
                         fpack(wb.x, wb.y), fpack(wb.z, wb.w)};
#pragma unroll
            for (int i = 0; i < 8; i++)
#pragma unroll
                for (int j = 0; j < 4; j++)
                    fma2(acc[i][j], w2[j], xd[i]);
        }
        __syncthreads();
    }

#pragma unroll
    for (int i = 0; i < 8; i++)
#pragma unroll
        for (int j = 0; j < 4; j++) {
            float lo, hi; funpack(acc[i][j], lo, hi);
            int n = nb + n0 + 2 * j;
            float* p = &g_h[(size_t)side * (B_ * 256) + (size_t)(b0 + i) * 256 + n];
            p[0] = leaky(lo + Bp[n]);
            p[1] = leaky(hi + Bp[n + 1]);
        }
}

// ============================================================================
// heads + quat distance + mean
// ============================================================================
__global__ void heads2_k(const float* __restrict__ wl2, const float* __restrict__ bl2,
                         const float* __restrict__ wr2, const float* __restrict__ br2,
                         const float* __restrict__ lt,  const float* __restrict__ rt) {
    int b = blockIdx.x, t = threadIdx.x;
    __shared__ float hl[256], hr[256], q[8];
    hl[t] = g_h[(size_t)b * 256 + t];
    hr[t] = g_h[(size_t)(B_ * 256) + (size_t)b * 256 + t];
    __syncthreads();

    int wrp = t >> 5, lane = t & 31;
    const float* w   = (wrp < 4) ? wl2 : wr2;
    const float* src = (wrp < 4) ? hl : hr;
    int i = wrp & 3;
    float s = 0.f;
    for (int j = lane; j < 256; j += 32) s += w[i * 256 + j] * src[j];
#pragma unroll
    for (int off = 16; off > 0; off >>= 1) s += __shfl_down_sync(0xffffffffu, s, off);
    if (lane == 0) q[wrp] = s + ((wrp < 4) ? bl2[i] : br2[i]);
    __syncthreads();

    if (t == 0) {
#pragma unroll
        for (int side = 0; side < 2; side++) {
            float qw = q[side * 4 + 0], qx = q[side * 4 + 1];
            float qy = q[side * 4 + 2], qz = q[side * 4 + 3];
            float nn = sqrtf(qw * qw + qx * qx + qy * qy + qz * qz);
            nn = fmaxf(nn, 1e-12f);
            qw /= nn; qx /= nn; qy /= nn; qz /= nn;
            const float* tgt = (side == 0 ? lt : rt) + (size_t)b * 4;
            float rw = tgt[0], rx = -tgt[1], ry = -tgt[2], rz = -tgt[3];
            float tw = qw * rw - qx * rx - qy * ry - qz * rz;
            float tx = qw * rx + qx * rw + qy * rz - qz * ry;
            float ty = qw * ry - qx * rz + qy * rw + qz * rx;
            float tz = qw * rz + qx * ry - qy * rx + qz * rw;
            float ang = 2.f * atan2f(sqrtf(tx * tx + ty * ty + tz * tz + 1e-12f), fabsf(tw));
            g_ang[side * B_ + b] = ang;
        }
    }
}

__global__ void mean_k(float* __restrict__ out) {
    __shared__ float sl[128], sr[128];
    int t = threadIdx.x;
    sl[t] = g_ang[t];
    sr[t] = g_ang[128 + t];
    __syncthreads();
    for (int s = 64; s > 0; s >>= 1) {
        if (t < s) { sl[t] += sl[t + s]; sr[t] += sr[t + s]; }
        __syncthreads();
    }
    if (t == 0) { out[0] = sl[0] * (1.f / 128.f); out[1] = sr[0] * (1.f / 128.f); }
}

// ============================================================================
extern "C" void kernel_launch(void* const* d_in, const int* in_sizes, int n_in,
                              void* d_out, int out_size) {
    (void)in_sizes; (void)n_in; (void)out_size;
    const float* left  = (const float*)d_in[0];
    const float* right = (const float*)d_in[1];
    const float* lt    = (const float*)d_in[2];
    const float* rt    = (const float*)d_in[3];
    const float* w6[5] = {(const float*)d_in[4],  (const float*)d_in[6],
                          (const float*)d_in[8],  (const float*)d_in[10],
                          (const float*)d_in[12]};
    const float* b6[5] = {(const float*)d_in[5],  (const float*)d_in[7],
                          (const float*)d_in[9],  (const float*)d_in[11],
                          (const float*)d_in[13]};
    const float* wfc1 = (const float*)d_in[14];
    const float* bfc1 = (const float*)d_in[15];
    const float* wl1  = (const float*)d_in[16];
    const float* bl1  = (const float*)d_in[17];
    const float* wr1  = (const float*)d_in[18];
    const float* br1  = (const float*)d_in[19];
    const float* wl2  = (const float*)d_in[20];
    const float* bl2  = (const float*)d_in[21];
    const float* wr2  = (const float*)d_in[22];
    const float* br2  = (const float*)d_in[23];
    float* out = (float*)d_out;

    static cudaStream_t s2 = nullptr;
    static cudaEvent_t evFork = nullptr, evW = nullptr, evJoin = nullptr;
    if (s2 == nullptr) {
        cudaStreamCreateWithFlags(&s2, cudaStreamNonBlocking);
        cudaEventCreateWithFlags(&evFork, cudaEventDisableTiming);
        cudaEventCreateWithFlags(&evW, cudaEventDisableTiming);
        cudaEventCreateWithFlags(&evJoin, cudaEventDisableTiming);
        cudaFuncSetAttribute(corr_k, cudaFuncAttributeMaxDynamicSharedMemorySize,
                             2 * CORR_STG * 4);
        cudaFuncSetAttribute(convB64_k, cudaFuncAttributeMaxDynamicSharedMemorySize,
                             2 * STG_W * 4);
        cudaFuncSetAttribute(fc1B_k, cudaFuncAttributeMaxDynamicSharedMemorySize,
                             F1_NSTG * F1_STW * 4);
    }

    const int INO[5]   = {448, 320, 192, 96, 32};
    const int OUTO[5]  = {320, 192, 96, 32, 0};
    const int OCL[5]   = {128, 128, 96, 64, 32};
    const int OCT64[5] = {2, 2, 2, 1, 1};
    const int CHK[5]   = {6, 14, 22, 28, 32};
    const int WBASE[5] = {0, 24, 80, 146, 202};

    // main chain first: corr gets the machine immediately
    cudaEventRecord(evFork, 0);
    corr_k<<<B_, 576, 2 * CORR_STG * 4>>>(left, right);

    // side chain on s2 fills SM gaps during corr + convs
    cudaStreamWaitEvent(s2, evFork, 0);
    wprep_all<<<234, 256, 0, s2>>>(w6[0], w6[1], w6[2], w6[3], w6[4]);
    cudaEventRecord(evW, s2);
    fc1wprep_k<<<dim3(8, KSPLIT), 256, 0, s2>>>(wfc1);
    cudaEventRecord(evJoin, s2);

    // convs need conv weights (evW) + corr (stream order)
    cudaStreamWaitEvent(0, evW, 0);
    for (int l = 0; l < 5; l++)
        convB64_k<<<dim3(B_, OCT64[l]), 256, 2 * STG_W * 4>>>(
            b6[l], CHK[l], WBASE[l], INO[l] >> 4, OUTO[l], OCL[l]);

    // join before fc1 consumes g_Wfb
    cudaStreamWaitEvent(0, evJoin, 0);
    fc1B_k<<<dim3(8, KSPLIT), 256, F1_NSTG * F1_STW * 4>>>();
    fc1red_k<<<256, 256>>>(bfc1);
    l1r1_k<<<dim3(2, 2), 256>>>(wl1, bl1, wr1, br1);
    heads2_k<<<B_, 256>>>(wl2, bl2, wr2, br2, lt, rt);
    mean_k<<<1, 128>>>(out);
}